// round 12
// baseline (speedup 1.0000x reference)
#include <cuda_runtime.h>

// Problem constants (fixed by the reference: B=2, C=8, L=256, D=128)
#define B_  2
#define C_  8
#define L_  256
#define D_  128
#define TILE 32          // 32x32 output tile per block
#define THREADS 256      // 16 (ti: row-pairs) x 16 (tj: col-pairs); 2x2 out each

__device__ __forceinline__ float rcp_fast(float x) {
    float y; asm("rcp.approx.f32 %0, %1;" : "=f"(y) : "f"(x)); return y;
}
__device__ __forceinline__ float ex2_fast(float x) {
    float y; asm("ex2.approx.f32 %0, %1;" : "=f"(y) : "f"(x)); return y;
}

#define TWO_LOG2E 2.885390081777927f   // 2 * log2(e)

// tanh(s+e) = 1 - 2/(1 + exp(2s)exp(2e))  =>  out = vsum - 2 * Σ_d v_d/(1+A·B)
//
// smem paired layout (one LDS.128 serves 2 d-values x 2 rows):
//   Ap[d2][rp] = float4( A(2d2,2rp), A(2d2,2rp+1), A(2d2+1,2rp), A(2d2+1,2rp+1) )
//   Bp same for B.  vp[d2] = ( v[2d2], v[2d2+1] ).
__global__ __launch_bounds__(THREADS)
void Add_Attn_Layer_59055800320841_kernel(const float* __restrict__ S,
                                          const float* __restrict__ E,
                                          const float* __restrict__ V,
                                          float* __restrict__ out) {
    __shared__ float4 Ap[(D_ / 2) * (TILE / 2)];   // 16 KB
    __shared__ float4 Bp[(D_ / 2) * (TILE / 2)];   // 16 KB
    __shared__ float2 vp[D_ / 2];
    __shared__ float  vsum_s;

    const int bc = blockIdx.z;            // b*C + c   (0..15)
    const int i0 = blockIdx.y * TILE;
    const int j0 = blockIdx.x * TILE;

    const float* Sbase = S + (size_t)bc * L_ * D_ + (size_t)i0 * D_;
    const float* Ebase = E + (size_t)bc * L_ * D_ + (size_t)j0 * D_;

    const int tid = threadIdx.x;

    if (tid < D_ / 2) {
        const float2 v2 = *reinterpret_cast<const float2*>(V + 2 * tid);
        vp[tid] = v2;
    }
    if (tid < 32) {
        float s = V[tid] + V[tid + 32] + V[tid + 64] + V[tid + 96];
        #pragma unroll
        for (int o = 16; o > 0; o >>= 1) s += __shfl_xor_sync(0xffffffffu, s, o);
        if (tid == 0) vsum_s = s;
    }

    // Load + transpose + exponentiate into the paired float4 layout.
    float* Apf = reinterpret_cast<float*>(Ap);
    float* Bpf = reinterpret_cast<float*>(Bp);
    #pragma unroll
    for (int idx = tid; idx < TILE * (D_ / 4); idx += THREADS) {
        const int row = idx & (TILE - 1);
        const int d4  = idx >> 5;                 // d = 4*d4 + q
        const float4 sv = *reinterpret_cast<const float4*>(Sbase + row * D_ + d4 * 4);
        const float4 ev = *reinterpret_cast<const float4*>(Ebase + row * D_ + d4 * 4);
        const int rp = row >> 1, rb = row & 1;
        #pragma unroll
        for (int q = 0; q < 4; q++) {
            const int d2   = 2 * d4 + (q >> 1);
            const int off  = (d2 * (TILE / 2) + rp) * 4 + (q & 1) * 2 + rb;
            const float fs = (q == 0) ? sv.x : (q == 1) ? sv.y : (q == 2) ? sv.z : sv.w;
            const float fe = (q == 0) ? ev.x : (q == 1) ? ev.y : (q == 2) ? ev.z : ev.w;
            Apf[off] = ex2_fast(fs * TWO_LOG2E);
            Bpf[off] = ex2_fast(fe * TWO_LOG2E);
        }
    }
    __syncthreads();

    // Thread -> 2 rows (2*ti, 2*ti+1) x 2 cols (2*tj, 2*tj+1)
    const int tj = tid & 15;
    const int ti = tid >> 4;

    // Separate accumulators for the two d-parities (merged at the end).
    float e00 = 0.f, e01 = 0.f, e10 = 0.f, e11 = 0.f;   // even d: MUFU rcp
    float o00 = 0.f, o01 = 0.f, o10 = 0.f, o11 = 0.f;   // odd d: Halley

    #pragma unroll 4
    for (int d2 = 0; d2 < D_ / 2; d2++) {
        const float4 a = Ap[d2 * (TILE / 2) + ti];   // (aev_r0, aev_r1, aod_r0, aod_r1)
        const float4 b = Bp[d2 * (TILE / 2) + tj];   // (bev_c0, bev_c1, bod_c0, bod_c1)
        const float2 v2 = vp[d2];

        // ---------- even d = 2*d2 : MUFU rcp (3 instr/elem) ----------
        e00 = fmaf(v2.x, rcp_fast(fmaf(a.x, b.x, 1.0f)), e00);
        e01 = fmaf(v2.x, rcp_fast(fmaf(a.x, b.y, 1.0f)), e01);
        e10 = fmaf(v2.x, rcp_fast(fmaf(a.y, b.x, 1.0f)), e10);
        e11 = fmaf(v2.x, rcp_fast(fmaf(a.y, b.y, 1.0f)), e11);

        // ---------- odd d = 2*d2+1 : magic seed + 1 Halley (6 instr/elem) ----
        #pragma unroll
        for (int k = 0; k < 4; k++) {
            const float aa = (k < 2) ? a.z : a.w;
            const float bb = (k & 1) ? b.w : b.z;
            const float x  = fmaf(aa, bb, 1.0f);              // x >= 1
            const float y0 = __uint_as_float(0x7EF311C3u - __float_as_uint(x));
            const float e  = fmaf(x, -y0, 1.0f);              // e = 1 - x*y0, |e| < ~5%
            const float g  = fmaf(e, e, e);                   // e + e^2
            const float y1 = fmaf(y0, g, y0);                 // y0*(1+e+e^2): err e^3
            if (k == 0) o00 = fmaf(v2.y, y1, o00);
            else if (k == 1) o01 = fmaf(v2.y, y1, o01);
            else if (k == 2) o10 = fmaf(v2.y, y1, o10);
            else             o11 = fmaf(v2.y, y1, o11);
        }
    }

    // out = vsum - 2 * (even + odd)
    const float vsum = vsum_s;
    const float t00 = e00 + o00, t01 = e01 + o01;
    const float t10 = e10 + o10, t11 = e11 + o11;

    const int b = bc >> 3;
    const int c = bc & 7;
    const int i = i0 + 2 * ti;
    const int j = j0 + 2 * tj;
    float* o = out + (((size_t)b * L_ + i) * L_ + j) * C_ + c;
    const size_t rs = (size_t)L_ * C_;   // i -> i+1
    o[0]       = fmaf(-2.0f, t00, vsum);
    o[C_]      = fmaf(-2.0f, t01, vsum);
    o[rs]      = fmaf(-2.0f, t10, vsum);
    o[rs + C_] = fmaf(-2.0f, t11, vsum);
}

extern "C" void kernel_launch(void* const* d_in, const int* in_sizes, int n_in,
                              void* d_out, int out_size) {
    (void)in_sizes; (void)n_in; (void)out_size;
    const float* S = (const float*)d_in[0];   // start_hidden [B,C,L,D]
    const float* E = (const float*)d_in[1];   // end_hidden   [B,C,L,D]
    const float* V = (const float*)d_in[2];   // v [D]
    float* out = (float*)d_out;               // [B,L,L,C] float32

    dim3 grid(L_ / TILE, L_ / TILE, B_ * C_); // (8, 8, 16) = 1024 blocks
    Add_Attn_Layer_59055800320841_kernel<<<grid, THREADS>>>(S, E, V, out);
}

// round 13
// speedup vs baseline: 1.0842x; 1.0842x over previous
#include <cuda_runtime.h>

// Problem constants (fixed by the reference: B=2, C=8, L=256, D=128)
#define B_  2
#define C_  8
#define L_  256
#define D_  128
#define TILE 32          // 32x32 output tile per block
#define THREADS 256      // 16 (ti: row-pairs) x 16 (tj: col-pairs); 2x2 out each

// 8 groups of 8 d2-pairs; in each group the first 5 d2 go through the
// tanh/MUFU path, the last 3 d2 through the exp-identity pair-combined
// reciprocal path (one MUFU rcp per TWO d's). LP-balances MUFU vs fma pipe.
#define NG   8
#define TD2  5
#define PD2  3
#define NT_SLOTS (NG * TD2)   // 40 tanh d2-slots (80 d's)
#define NP_SLOTS (NG * PD2)   // 24 pair d2-slots (48 d's)

__device__ __forceinline__ float tanh_fast(float x) {
    float y; asm("tanh.approx.f32 %0, %1;" : "=f"(y) : "f"(x)); return y;
}
__device__ __forceinline__ float rcp_fast(float x) {
    float y; asm("rcp.approx.f32 %0, %1;" : "=f"(y) : "f"(x)); return y;
}
__device__ __forceinline__ float ex2_fast(float x) {
    float y; asm("ex2.approx.f32 %0, %1;" : "=f"(y) : "f"(x)); return y;
}

#define TWO_LOG2E 2.885390081777927f   // 2 * log2(e)

// Paired float4 layout (proven in R11): word [slot][rowpair] holds
// ( val(d0, 2rp), val(d0, 2rp+1), val(d1, 2rp), val(d1, 2rp+1) )
// so one LDS.128 feeds both d's of a d2 for a row-pair.
__global__ __launch_bounds__(THREADS)
void Add_Attn_Layer_59055800320841_kernel(const float* __restrict__ S,
                                          const float* __restrict__ E,
                                          const float* __restrict__ V,
                                          float* __restrict__ out) {
    __shared__ float4 Tsp[NT_SLOTS * 16];   // raw s, tanh path   (10.0 KB)
    __shared__ float4 Tep[NT_SLOTS * 16];   // raw e              (10.0 KB)
    __shared__ float4 Apc[NP_SLOTS * 16];   // exp(2s), pair path ( 6.0 KB)
    __shared__ float4 Bpc[NP_SLOTS * 16];   // exp(2e)            ( 6.0 KB)
    __shared__ float2 vt2[NT_SLOTS];
    __shared__ float2 vp2[NP_SLOTS];
    __shared__ float  vsp_s;                // sum of v over pair-path d's

    const int bc = blockIdx.z;            // b*C + c   (0..15)
    const int i0 = blockIdx.y * TILE;
    const int j0 = blockIdx.x * TILE;

    const float* Sbase = S + (size_t)bc * L_ * D_ + (size_t)i0 * D_;
    const float* Ebase = E + (size_t)bc * L_ * D_ + (size_t)j0 * D_;

    const int tid = threadIdx.x;

    // v routing: d2 = tid (0..63)
    if (tid < D_ / 2) {
        const float2 v2 = *reinterpret_cast<const float2*>(V + 2 * tid);
        const int g = tid >> 3, pos = tid & 7;
        if (pos < TD2) vt2[g * TD2 + pos] = v2;
        else           vp2[g * PD2 + (pos - TD2)] = v2;
    }
    // vsum over the pair-path d's only (lanes 0..23, one pair-slot each)
    if (tid < 32) {
        float s = 0.f;
        if (tid < NP_SLOTS) {
            const int g = tid / PD2, r = tid - g * PD2;
            const int d2 = g * 8 + TD2 + r;
            s = V[2 * d2] + V[2 * d2 + 1];
        }
        #pragma unroll
        for (int o = 16; o > 0; o >>= 1) s += __shfl_xor_sync(0xffffffffu, s, o);
        if (tid == 0) vsp_s = s;
    }

    // Load + transpose into the two path-specific paired layouts.
    float* Tspf = reinterpret_cast<float*>(Tsp);
    float* Tepf = reinterpret_cast<float*>(Tep);
    float* Apcf = reinterpret_cast<float*>(Apc);
    float* Bpcf = reinterpret_cast<float*>(Bpc);
    #pragma unroll
    for (int idx = tid; idx < TILE * (D_ / 4); idx += THREADS) {
        const int row = idx & (TILE - 1);
        const int d4  = idx >> 5;                 // d = 4*d4 + q
        const float4 sv = *reinterpret_cast<const float4*>(Sbase + row * D_ + d4 * 4);
        const float4 ev = *reinterpret_cast<const float4*>(Ebase + row * D_ + d4 * 4);
        const int rp = row >> 1, rb = row & 1;
        #pragma unroll
        for (int q = 0; q < 4; q++) {
            const int d   = 4 * d4 + q;
            const int d2  = d >> 1;
            const int g   = d2 >> 3, pos = d2 & 7;
            const float fs = (q == 0) ? sv.x : (q == 1) ? sv.y : (q == 2) ? sv.z : sv.w;
            const float fe = (q == 0) ? ev.x : (q == 1) ? ev.y : (q == 2) ? ev.z : ev.w;
            if (pos < TD2) {
                const int off = ((g * TD2 + pos) * 16 + rp) * 4 + (d & 1) * 2 + rb;
                Tspf[off] = fs;
                Tepf[off] = fe;
            } else {
                const int off = ((g * PD2 + pos - TD2) * 16 + rp) * 4 + (d & 1) * 2 + rb;
                Apcf[off] = ex2_fast(fs * TWO_LOG2E);
                Bpcf[off] = ex2_fast(fe * TWO_LOG2E);
            }
        }
    }
    __syncthreads();

    // Thread -> 2 rows (2*ti, 2*ti+1) x 2 cols (2*tj, 2*tj+1)
    const int tj = tid & 15;
    const int ti = tid >> 4;

    float t00 = 0.f, t01 = 0.f, t10 = 0.f, t11 = 0.f;   // tanh-path: Σ v·tanh
    float p00 = 0.f, p01 = 0.f, p10 = 0.f, p11 = 0.f;   // pair-path: Σ P·rcp(Q)

    #pragma unroll 2
    for (int g = 0; g < NG; g++) {
        // ----- tanh path: 5 d2-slots, 1 MUFU per element -----
        #pragma unroll
        for (int pos = 0; pos < TD2; pos++) {
            const int slot = g * TD2 + pos;
            const float4 s4 = Tsp[slot * 16 + ti];   // (sd0_r0, sd0_r1, sd1_r0, sd1_r1)
            const float4 e4 = Tep[slot * 16 + tj];   // (ed0_c0, ed0_c1, ed1_c0, ed1_c1)
            const float2 v2 = vt2[slot];
            t00 = fmaf(v2.x, tanh_fast(s4.x + e4.x), t00);
            t01 = fmaf(v2.x, tanh_fast(s4.x + e4.y), t01);
            t10 = fmaf(v2.x, tanh_fast(s4.y + e4.x), t10);
            t11 = fmaf(v2.x, tanh_fast(s4.y + e4.y), t11);
            t00 = fmaf(v2.y, tanh_fast(s4.z + e4.z), t00);
            t01 = fmaf(v2.y, tanh_fast(s4.z + e4.w), t01);
            t10 = fmaf(v2.y, tanh_fast(s4.w + e4.z), t10);
            t11 = fmaf(v2.y, tanh_fast(s4.w + e4.w), t11);
        }
        // ----- pair path: 3 d2-slots, 1 MUFU per TWO elements -----
        // v0/x0 + v1/x1 = (v0*x1 + v1*x0) * rcp(x0*x1),  x = 1 + A*B
        #pragma unroll
        for (int ps = 0; ps < PD2; ps++) {
            const int slot = g * PD2 + ps;
            const float4 a = Apc[slot * 16 + ti];
            const float4 b = Bpc[slot * 16 + tj];
            const float2 v2 = vp2[slot];
            {   // cell (r0, c0)
                const float x0 = fmaf(a.x, b.x, 1.0f), x1 = fmaf(a.z, b.z, 1.0f);
                const float P  = fmaf(v2.y, x0, v2.x * x1);
                p00 = fmaf(P, rcp_fast(x0 * x1), p00);
            }
            {   // cell (r0, c1)
                const float x0 = fmaf(a.x, b.y, 1.0f), x1 = fmaf(a.z, b.w, 1.0f);
                const float P  = fmaf(v2.y, x0, v2.x * x1);
                p01 = fmaf(P, rcp_fast(x0 * x1), p01);
            }
            {   // cell (r1, c0)
                const float x0 = fmaf(a.y, b.x, 1.0f), x1 = fmaf(a.w, b.z, 1.0f);
                const float P  = fmaf(v2.y, x0, v2.x * x1);
                p10 = fmaf(P, rcp_fast(x0 * x1), p10);
            }
            {   // cell (r1, c1)
                const float x0 = fmaf(a.y, b.y, 1.0f), x1 = fmaf(a.w, b.w, 1.0f);
                const float P  = fmaf(v2.y, x0, v2.x * x1);
                p11 = fmaf(P, rcp_fast(x0 * x1), p11);
            }
        }
    }

    // pair-path contribution: Σ v (1 - 2/x) = vsp - 2 * Σ v/x
    const float vsp = vsp_s;
    const float o00 = t00 + fmaf(-2.0f, p00, vsp);
    const float o01 = t01 + fmaf(-2.0f, p01, vsp);
    const float o10 = t10 + fmaf(-2.0f, p10, vsp);
    const float o11 = t11 + fmaf(-2.0f, p11, vsp);

    const int b = bc >> 3;
    const int c = bc & 7;
    const int i = i0 + 2 * ti;
    const int j = j0 + 2 * tj;
    float* o = out + (((size_t)b * L_ + i) * L_ + j) * C_ + c;
    const size_t rs = (size_t)L_ * C_;   // i -> i+1
    o[0]       = o00;
    o[C_]      = o01;
    o[rs]      = o10;
    o[rs + C_] = o11;
}

extern "C" void kernel_launch(void* const* d_in, const int* in_sizes, int n_in,
                              void* d_out, int out_size) {
    (void)in_sizes; (void)n_in; (void)out_size;
    const float* S = (const float*)d_in[0];   // start_hidden [B,C,L,D]
    const float* E = (const float*)d_in[1];   // end_hidden   [B,C,L,D]
    const float* V = (const float*)d_in[2];   // v [D]
    float* out = (float*)d_out;               // [B,L,L,C] float32

    dim3 grid(L_ / TILE, L_ / TILE, B_ * C_); // (8, 8, 16) = 1024 blocks
    Add_Attn_Layer_59055800320841_kernel<<<grid, THREADS>>>(S, E, V, out);
}

// round 14
// speedup vs baseline: 1.2380x; 1.1419x over previous
#include <cuda_runtime.h>

// Problem constants (fixed by the reference: B=2, C=8, L=256, D=128)
#define B_  2
#define C_  8
#define L_  256
#define D_  128
#define TILE 32          // 32x32 output tile per block
#define THREADS 256      // 16 (ti: row-pairs) x 16 (tj: col-pairs); 2x2 out each

__device__ __forceinline__ float tanh_fast(float x) {
    float y; asm("tanh.approx.f32 %0, %1;" : "=f"(y) : "f"(x)); return y;
}

// Paired float4 layout: word [d2][rowpair] holds
//   ( val(2*d2, 2rp), val(2*d2, 2rp+1), val(2*d2+1, 2rp), val(2*d2+1, 2rp+1) )
// so ONE LDS.128 per operand feeds both d's of a d2 for a row/col-pair:
// 3 LDS per 8 tanh evaluations (0.375 LDS/elem, half of R3's 0.75).
__global__ __launch_bounds__(THREADS)
void Add_Attn_Layer_59055800320841_kernel(const float* __restrict__ S,
                                          const float* __restrict__ E,
                                          const float* __restrict__ V,
                                          float* __restrict__ out) {
    __shared__ float4 Ap[(D_ / 2) * (TILE / 2)];   // s, paired  (16 KB)
    __shared__ float4 Bp[(D_ / 2) * (TILE / 2)];   // e, paired  (16 KB)
    __shared__ float2 vp[D_ / 2];

    const int bc = blockIdx.z;            // b*C + c   (0..15)
    const int i0 = blockIdx.y * TILE;
    const int j0 = blockIdx.x * TILE;

    const float* Sbase = S + (size_t)bc * L_ * D_ + (size_t)i0 * D_;
    const float* Ebase = E + (size_t)bc * L_ * D_ + (size_t)j0 * D_;

    const int tid = threadIdx.x;

    if (tid < D_ / 2) {
        vp[tid] = *reinterpret_cast<const float2*>(V + 2 * tid);
    }

    // Load + transpose into the paired float4 layout (raw values, no math).
    // Lanes take consecutive rows at the same d4 -> coalesced 16B gmem loads.
    float* Apf = reinterpret_cast<float*>(Ap);
    float* Bpf = reinterpret_cast<float*>(Bp);
    #pragma unroll
    for (int idx = tid; idx < TILE * (D_ / 4); idx += THREADS) {
        const int row = idx & (TILE - 1);
        const int d4  = idx >> 5;                 // d = 4*d4 + q
        const float4 sv = *reinterpret_cast<const float4*>(Sbase + row * D_ + d4 * 4);
        const float4 ev = *reinterpret_cast<const float4*>(Ebase + row * D_ + d4 * 4);
        const int rp = row >> 1, rb = row & 1;
        #pragma unroll
        for (int q = 0; q < 4; q++) {
            const int d2  = 2 * d4 + (q >> 1);
            const int off = (d2 * (TILE / 2) + rp) * 4 + (q & 1) * 2 + rb;
            Apf[off] = (q == 0) ? sv.x : (q == 1) ? sv.y : (q == 2) ? sv.z : sv.w;
            Bpf[off] = (q == 0) ? ev.x : (q == 1) ? ev.y : (q == 2) ? ev.z : ev.w;
        }
    }
    __syncthreads();

    // Thread -> 2 rows (2*ti, 2*ti+1) x 2 cols (2*tj, 2*tj+1)
    const int tj = tid & 15;
    const int ti = tid >> 4;

    float a00 = 0.f, a01 = 0.f, a10 = 0.f, a11 = 0.f;

    const float4* ap = Ap + ti;
    const float4* bp = Bp + tj;

    #pragma unroll 4
    for (int d2 = 0; d2 < D_ / 2; d2++) {
        const float4 s4 = ap[d2 * (TILE / 2)];   // (sd0_r0, sd0_r1, sd1_r0, sd1_r1)
        const float4 e4 = bp[d2 * (TILE / 2)];   // (ed0_c0, ed0_c1, ed1_c0, ed1_c1)
        const float2 v2 = vp[d2];
        // d = 2*d2
        a00 = fmaf(v2.x, tanh_fast(s4.x + e4.x), a00);
        a01 = fmaf(v2.x, tanh_fast(s4.x + e4.y), a01);
        a10 = fmaf(v2.x, tanh_fast(s4.y + e4.x), a10);
        a11 = fmaf(v2.x, tanh_fast(s4.y + e4.y), a11);
        // d = 2*d2+1
        a00 = fmaf(v2.y, tanh_fast(s4.z + e4.z), a00);
        a01 = fmaf(v2.y, tanh_fast(s4.z + e4.w), a01);
        a10 = fmaf(v2.y, tanh_fast(s4.w + e4.z), a10);
        a11 = fmaf(v2.y, tanh_fast(s4.w + e4.w), a11);
    }

    // out[b][i][j][c], c fastest; bc = b*C + c
    const int b = bc >> 3;
    const int c = bc & 7;
    const int i = i0 + 2 * ti;
    const int j = j0 + 2 * tj;
    float* o = out + (((size_t)b * L_ + i) * L_ + j) * C_ + c;
    const size_t rs = (size_t)L_ * C_;   // i -> i+1
    o[0]       = a00;
    o[C_]      = a01;
    o[rs]      = a10;
    o[rs + C_] = a11;
}

extern "C" void kernel_launch(void* const* d_in, const int* in_sizes, int n_in,
                              void* d_out, int out_size) {
    (void)in_sizes; (void)n_in; (void)out_size;
    const float* S = (const float*)d_in[0];   // start_hidden [B,C,L,D]
    const float* E = (const float*)d_in[1];   // end_hidden   [B,C,L,D]
    const float* V = (const float*)d_in[2];   // v [D]
    float* out = (float*)d_out;               // [B,L,L,C] float32

    dim3 grid(L_ / TILE, L_ / TILE, B_ * C_); // (8, 8, 16) = 1024 blocks
    Add_Attn_Layer_59055800320841_kernel<<<grid, THREADS>>>(S, E, V, out);
}